// round 2
// baseline (speedup 1.0000x reference)
#include <cuda_runtime.h>

// AdaptiveSudokuLoss: ce + 0.5 * constraint + 0.1 * entropy
// outputs: (B, 81, 9) fp32, targets: (B, 81) int32 (JAX downcasts int64 w/o x64),
// out: scalar fp32
//
// Kernel 1: each block = 96 threads, PER_BLOCK batch elements. Threads 0..80
//           each own one cell. Softmax in registers; probs staged in smem for
//           the 27 constraint sums. Per-block partials -> __device__ arrays.
// Kernel 2: single block, deterministic fixed-order reduction + final combine.

#define PER_BLOCK 8
#define THREADS 96
#define MAX_PARTIAL 16384

__device__ float g_ce[MAX_PARTIAL];
__device__ float g_cons[MAX_PARTIAL];
__device__ float g_conf[MAX_PARTIAL];

__global__ __launch_bounds__(THREADS)
void sudoku_loss_main(const float* __restrict__ outp,
                      const int* __restrict__ tgt,   // int32 targets
                      int Bn)
{
    __shared__ float sp[81 * 9];   // probs for one batch element
    const int tid = threadIdx.x;

    float ce_acc = 0.f, cons_acc = 0.f, conf_acc = 0.f;

    const int base_b = blockIdx.x * PER_BLOCK;
    #pragma unroll 1
    for (int k = 0; k < PER_BLOCK; k++) {
        const int b = base_b + k;
        if (b < Bn) {
            // -------- phase 1: per-cell softmax, ce, entropy; probs -> smem ----
            if (tid < 81) {
                const float* x = outp + ((size_t)b * 81 + tid) * 9;
                float v[9];
                #pragma unroll
                for (int j = 0; j < 9; j++) v[j] = x[j];

                float m = v[0];
                #pragma unroll
                for (int j = 1; j < 9; j++) m = fmaxf(m, v[j]);

                float e[9];
                float s = 0.f;
                #pragma unroll
                for (int j = 0; j < 9; j++) { e[j] = __expf(v[j] - m); s += e[j]; }

                const float inv = __frcp_rn(s);
                float sx = 0.f;
                #pragma unroll
                for (int j = 0; j < 9; j++) {
                    const float p = e[j] * inv;
                    sp[tid * 9 + j] = p;
                    sx = fmaf(p, v[j], sx);
                }
                const float lse = m + __logf(s);

                const int t = tgt[(size_t)b * 81 + tid];

                // select x[t] without dynamic register indexing (keeps v in regs)
                float xt = 0.f;
                #pragma unroll
                for (int j = 0; j < 9; j++) xt += (j == t) ? v[j] : 0.f;

                ce_acc   += lse - xt;   // -logp[target]
                conf_acc += lse - sx;   // entropy = -(sum p*logp)
            }
            __syncthreads();

            // -------- phase 2: 27 constraint sums (thread = (idx, digit)) -----
            if (tid < 81) {
                const int idx = tid / 9;
                const int d   = tid - idx * 9;

                float rs = 0.f, cs = 0.f, bs = 0.f;
                #pragma unroll
                for (int c = 0; c < 9; c++) rs += sp[(idx * 9 + c) * 9 + d];
                #pragma unroll
                for (int r = 0; r < 9; r++) cs += sp[(r * 9 + idx) * 9 + d];
                const int br = idx / 3, bc = idx - br * 3;
                #pragma unroll
                for (int dr = 0; dr < 3; dr++)
                    #pragma unroll
                    for (int dc = 0; dc < 3; dc++)
                        bs += sp[((br * 3 + dr) * 9 + (bc * 3 + dc)) * 9 + d];

                rs -= 1.f; cs -= 1.f; bs -= 1.f;
                cons_acc += rs * rs + cs * cs + bs * bs;
            }
            __syncthreads();
        }
    }

    // -------- block reduction: 3 scalars over 96 threads (3 full warps) ------
    #pragma unroll
    for (int o = 16; o > 0; o >>= 1) {
        ce_acc   += __shfl_down_sync(0xffffffffu, ce_acc,   o);
        cons_acc += __shfl_down_sync(0xffffffffu, cons_acc, o);
        conf_acc += __shfl_down_sync(0xffffffffu, conf_acc, o);
    }
    __shared__ float wr[3][3];
    const int wid = tid >> 5, lid = tid & 31;
    if (lid == 0) { wr[wid][0] = ce_acc; wr[wid][1] = cons_acc; wr[wid][2] = conf_acc; }
    __syncthreads();
    if (tid == 0) {
        g_ce[blockIdx.x]   = wr[0][0] + wr[1][0] + wr[2][0];
        g_cons[blockIdx.x] = wr[0][1] + wr[1][1] + wr[2][1];
        g_conf[blockIdx.x] = wr[0][2] + wr[1][2] + wr[2][2];
    }
}

__global__ __launch_bounds__(256)
void sudoku_loss_final(float* __restrict__ d_out, int nblocks, int Bn)
{
    __shared__ float sred[3 * 256];
    const int tid = threadIdx.x;
    float a = 0.f, b = 0.f, c = 0.f;
    for (int i = tid; i < nblocks; i += 256) {
        a += g_ce[i];
        b += g_cons[i];
        c += g_conf[i];
    }
    sred[tid] = a; sred[256 + tid] = b; sred[512 + tid] = c;
    __syncthreads();
    #pragma unroll
    for (int o = 128; o > 0; o >>= 1) {
        if (tid < o) {
            sred[tid]       += sred[tid + o];
            sred[256 + tid] += sred[256 + tid + o];
            sred[512 + tid] += sred[512 + tid + o];
        }
        __syncthreads();
    }
    if (tid == 0) {
        const float Ncells = (float)Bn * 81.0f;
        const float ce   = sred[0]   / Ncells;
        const float cons = sred[256] / ((float)Bn * 9.0f * 27.0f);
        const float conf = sred[512] / (Ncells + 1e-8f);
        d_out[0] = ce + 0.5f * cons + 0.1f * conf;
    }
}

extern "C" void kernel_launch(void* const* d_in, const int* in_sizes, int n_in,
                              void* d_out, int out_size)
{
    const float* outp = (const float*)d_in[0];   // (B, 81, 9) fp32
    const int*   tgt  = (const int*)d_in[1];     // (B, 81) int32
    float*       out  = (float*)d_out;

    const int Bn = in_sizes[0] / (81 * 9);
    int grid = (Bn + PER_BLOCK - 1) / PER_BLOCK;
    if (grid > MAX_PARTIAL) grid = MAX_PARTIAL;  // dataset: B=65536 -> 8192

    sudoku_loss_main<<<grid, THREADS>>>(outp, tgt, Bn);
    sudoku_loss_final<<<1, 256>>>(out, grid, Bn);
}